// round 5
// baseline (speedup 1.0000x reference)
#include <cuda_runtime.h>
#include <math.h>

// ---------------- constants ----------------
#define NC 80
#define M0 614400
#define M1 153600
#define M2 38400
#define MTOT 806400

#define N0 6000
#define N1 4000
#define N2 2000
#define NT 12000

#define EPSV 1e-7f

// block layout: warp-per-target blocks (8 warps each), then dense float4 blocks
#define T0_BLK 750            // 6000/8
#define T1_BLK 500            // 4000/8
#define T2_BLK 250            // 2000/8
#define T_BLOCKS (T0_BLK+T1_BLK+T2_BLK)      // 1500
#define D0_BLK 600            // 600*256 = 153600 = M0/4
#define D1_BLK 150            // 150*256 =  38400 = M1/4
#define D2_BLK 38             //  38*256 =   9728 >= 9600 = M2/4
#define D_BLOCKS (D0_BLK+D1_BLK+D2_BLK)      // 788
#define GRID_TOT (T_BLOCKS + D_BLOCKS)       // 2288

// ---------------- scratch (no allocations allowed) ----------------
__device__ float    g_tobj[MTOT];   // zero at load; tail restores to zero each run
__device__ int      g_cells[NT];
__device__ float    g_pTb[T_BLOCKS];
__device__ float    g_pTc[T_BLOCKS];
__device__ float    g_pTo[T_BLOCKS];
__device__ float    g_pD[D_BLOCKS];
__device__ unsigned g_ticket;       // zero at load; tail resets

// ---------------- params ----------------
struct P {
    const float* box[3]; const float* cnf[3]; const float* cls[3];
    const float* tbox[3]; const float* anc[3];
    const int* b[3]; const int* a[3]; const int* gy[3]; const int* gx[3]; const int* tc[3];
};

// ---------------- helpers ----------------
__device__ __forceinline__ float sp(float x) {   // softplus = bce(x,0), fast
    return fmaxf(x, 0.f) + __logf(1.f + __expf(-fabsf(x)));
}
__device__ __forceinline__ float sigf(float x) {
    return __fdividef(1.f, 1.f + __expf(-x));
}

__device__ __forceinline__ float ciou(float cx1, float cy1, float w1, float h1,
                                      float cx2, float cy2, float w2, float h2) {
    float x1a = cx1 - w1 * 0.5f, y1a = cy1 - h1 * 0.5f;
    float x2a = cx1 + w1 * 0.5f, y2a = cy1 + h1 * 0.5f;
    float x1b = cx2 - w2 * 0.5f, y1b = cy2 - h2 * 0.5f;
    float x2b = cx2 + w2 * 0.5f, y2b = cy2 + h2 * 0.5f;

    float iw = fmaxf(fminf(x2a, x2b) - fmaxf(x1a, x1b), 0.f);
    float ih = fmaxf(fminf(y2a, y2b) - fmaxf(y1a, y1b), 0.f);
    float inter = iw * ih;
    float uni = (x2a - x1a) * (y2a - y1a) + (x2b - x1b) * (y2b - y1b) - inter;
    float iou = __fdividef(inter, uni + EPSV);

    float cw = fmaxf(x2a, x2b) - fminf(x1a, x1b);
    float ch = fmaxf(y2a, y2b) - fminf(y1a, y1b);
    float diag = cw * cw + ch * ch + EPSV;
    float dx = (x1a + x2a) * 0.5f - (x1b + x2b) * 0.5f;
    float dy = (y1a + y2a) * 0.5f - (y1b + y2b) * 0.5f;
    float cent = dx * dx + dy * dy;

    float at = atanf(__fdividef(x2a - x1a, y2a - y1a + EPSV))
             - atanf(__fdividef(x2b - x1b, y2b - y1b + EPSV));
    const float C4PI2 = 4.0f / (float)(M_PI * M_PI);
    float v = C4PI2 * at * at;
    float alpha = __fdividef(v, v - iou + 1.f + EPSV);
    return iou - (__fdividef(cent, diag) + v * alpha);
}

// ---------------- per-scale compile-time constants ----------------
template<int SI> struct SC;
template<> struct SC<0> { static constexpr int DIM=80, OFF=0,     NSC=N0; static constexpr float W=4.0f/(float)M0; };
template<> struct SC<1> { static constexpr int DIM=40, OFF=M0,    NSC=N1; static constexpr float W=1.0f/(float)M1; };
template<> struct SC<2> { static constexpr int DIM=20, OFF=M0+M1, NSC=N2; static constexpr float W=0.4f/(float)M2; };

// ---------------- target block (warp per target), compile-time SI ----------
template<int SI>
__device__ __forceinline__ void target_block(const P& __restrict__ p, int bid0, unsigned bx) {
    __shared__ float sh[24];
    const int tid  = threadIdx.x;
    const int lane = tid & 31;
    const int wid  = tid >> 5;

    const int gt = ((int)bx - bid0) * 8 + wid           // scale-local target
                 ;
    const int t  = gt;                                   // local index within scale SI
    constexpr int DIM = SC<SI>::DIM;
    constexpr float INV_N  = 1.f / (float)SC<SI>::NSC;
    constexpr float INV_NC = 1.f / ((float)SC<SI>::NSC * (float)NC);

    // uniform index loads (broadcast LDG, constant-indexed params -> LDC)
    int bb = p.b[SI][t], aa = p.a[SI][t];
    int yy = p.gy[SI][t], xx = p.gx[SI][t];
    int tc = p.tc[SI][t];
    int base = ((bb * 3 + aa) * DIM + yy) * DIM + xx;

    // class-row softplus sum across lanes 0..19 (float4 each)
    const float4* crow = (const float4*)(p.cls[SI] + (size_t)base * NC);
    float4 x = make_float4(0.f, 0.f, 0.f, 0.f);
    float s = 0.f;
    if (lane < 20) {
        x = crow[lane];
        s = sp(x.x) + sp(x.y) + sp(x.z) + sp(x.w);
    }
    // extract x_tc from the already-loaded row
    float comp = (tc & 2) ? ((tc & 1) ? x.w : x.z) : ((tc & 1) ? x.y : x.x);
    float xtc  = __shfl_sync(0xffffffffu, comp, tc >> 2);

    #pragma unroll
    for (int o = 16; o; o >>= 1)
        s += __shfl_down_sync(0xffffffffu, s, o);

    if (lane == 0) {
        float4 br = ((const float4*)p.box[SI])[base];
        float2 an = ((const float2*)p.anc[SI])[t];
        float4 tb = ((const float4*)p.tbox[SI])[t];

        float px = sigf(br.x) * 2.f - 0.5f;
        float py = sigf(br.y) * 2.f - 0.5f;
        float sw = sigf(br.z) * 2.f;
        float shh = sigf(br.w) * 2.f;
        float pw = sw * sw * an.x;
        float ph = shh * shh * an.y;

        float ci = ciou(px, py, pw, ph, tb.x, tb.y, tb.z, tb.w);
        float v  = fmaxf(ci, 0.f);

        int cell = SC<SI>::OFF + base;
        float old = atomicExch(&g_tobj[cell], v);   // telescoping winner semantics
        int gidx = (SI == 0 ? 0 : (SI == 1 ? N0 : N0 + N1)) + t;
        g_cells[gidx] = cell;

        sh[wid]      = (1.f - ci) * INV_N;                      // lbox
        sh[8 + wid]  = (s - xtc) * INV_NC;                      // lcls
        sh[16 + wid] = p.cnf[SI][base] * (v - old) * SC<SI>::W; // lobj correction
    }
    __syncthreads();
    if (tid == 0) {
        float a = 0.f, b = 0.f, c = 0.f;
        #pragma unroll
        for (int i = 0; i < 8; i++) { a += sh[i]; b += sh[8 + i]; c += sh[16 + i]; }
        g_pTb[bx] = a; g_pTc[bx] = b; g_pTo[bx] = c;
    }
}

// ---------------- dense block (float4 softplus), compile-time SI -----------
template<int SI>
__device__ __forceinline__ void dense_block(const P& __restrict__ p, int db_local, unsigned bx) {
    __shared__ float sh[8];
    const int tid  = threadIdx.x;
    const int lane = tid & 31;
    const int wid  = tid >> 5;

    constexpr int Q = (SI == 0 ? M0 : (SI == 1 ? M1 : M2)) / 4;
    int i4 = db_local * 256 + tid;
    float acc = 0.f;
    if (SI != 2 || i4 < Q) {
        float4 x = ((const float4*)p.cnf[SI])[i4];
        acc = sp(x.x) + sp(x.y) + sp(x.z) + sp(x.w);
    }
    #pragma unroll
    for (int o = 16; o; o >>= 1)
        acc += __shfl_down_sync(0xffffffffu, acc, o);
    if (lane == 0) sh[wid] = acc;
    __syncthreads();
    if (tid == 0) {
        float a = 0.f;
        #pragma unroll
        for (int i = 0; i < 8; i++) a += sh[i];
        g_pD[bx - T_BLOCKS] = a * SC<SI>::W;
    }
}

// ---------------- fused kernel ----------------
__global__ void __launch_bounds__(256) k_fused(P p, float* __restrict__ out) {
    const unsigned bx = blockIdx.x;
    const int tid  = threadIdx.x;
    const int lane = tid & 31;
    const int wid  = tid >> 5;

    if (bx < T_BLOCKS) {
        if (bx < T0_BLK)              target_block<0>(p, 0, bx);
        else if (bx < T0_BLK + T1_BLK) target_block<1>(p, T0_BLK, bx);
        else                           target_block<2>(p, T0_BLK + T1_BLK, bx);
    } else {
        int db = (int)bx - T_BLOCKS;
        if (db < D0_BLK)               dense_block<0>(p, db, bx);
        else if (db < D0_BLK + D1_BLK) dense_block<1>(p, db - D0_BLK, bx);
        else                           dense_block<2>(p, db - D0_BLK - D1_BLK, bx);
    }

    // ===== last-block tail: cleanup + final reduce =====
    __shared__ unsigned s_rank;
    __threadfence();
    if (tid == 0) s_rank = atomicAdd(&g_ticket, 1u);
    __syncthreads();
    if (s_rank == GRID_TOT - 1) {
        __threadfence();
        // restore g_tobj to zero for next graph replay
        for (int i = tid; i < NT; i += 256) g_tobj[g_cells[i]] = 0.f;

        double lb = 0.0, lc = 0.0, lo = 0.0;
        for (int i = tid; i < T_BLOCKS; i += 256) {
            lb += (double)g_pTb[i];
            lc += (double)g_pTc[i];
            lo -= (double)g_pTo[i];
        }
        for (int i = tid; i < D_BLOCKS; i += 256) lo += (double)g_pD[i];

        #pragma unroll
        for (int o = 16; o; o >>= 1) {
            lb += __shfl_down_sync(0xffffffffu, lb, o);
            lc += __shfl_down_sync(0xffffffffu, lc, o);
            lo += __shfl_down_sync(0xffffffffu, lo, o);
        }
        __shared__ double shd[24];
        if (lane == 0) { shd[wid] = lb; shd[8 + wid] = lc; shd[16 + wid] = lo; }
        __syncthreads();
        if (tid == 0) {
            double b = 0.0, c = 0.0, o = 0.0;
            #pragma unroll
            for (int i = 0; i < 8; i++) { b += shd[i]; c += shd[8 + i]; o += shd[16 + i]; }
            out[0] = (float)(b * 1.6);    // 0.05 * 32
            out[1] = (float)(o * 22.4);   // 0.70 * 32
            out[2] = (float)(c * 9.6);    // 0.30 * 32
            g_ticket = 0;                 // reset for next replay
        }
    }
}

// ---------------- launch ----------------
extern "C" void kernel_launch(void* const* d_in, const int* in_sizes, int n_in,
                              void* d_out, int out_size) {
    // Disambiguate metadata ordering via in_sizes[3]:
    //  (A) reference-arg order -> in_sizes[3] == 24000 (tbox0)
    //  (B) setup_inputs insertion order per scale [box,cnf,cls,b,a,gy,gx,tcls,tbox,anc] -> 6000 (b0)
    P p;
    bool orderA = (n_in > 3 && in_sizes[3] == 24000);
    if (orderA) {
        for (int i = 0; i < 3; i++) {
            int f = 5 * i, g = 15 + 5 * i;
            p.box[i]  = (const float*)d_in[f + 0];
            p.cnf[i]  = (const float*)d_in[f + 1];
            p.cls[i]  = (const float*)d_in[f + 2];
            p.tbox[i] = (const float*)d_in[f + 3];
            p.anc[i]  = (const float*)d_in[f + 4];
            p.b[i]    = (const int*)d_in[g + 0];
            p.a[i]    = (const int*)d_in[g + 1];
            p.gy[i]   = (const int*)d_in[g + 2];
            p.gx[i]   = (const int*)d_in[g + 3];
            p.tc[i]   = (const int*)d_in[g + 4];
        }
    } else {
        for (int i = 0; i < 3; i++) {
            int q = 10 * i;
            p.box[i]  = (const float*)d_in[q + 0];
            p.cnf[i]  = (const float*)d_in[q + 1];
            p.cls[i]  = (const float*)d_in[q + 2];
            p.b[i]    = (const int*)d_in[q + 3];
            p.a[i]    = (const int*)d_in[q + 4];
            p.gy[i]   = (const int*)d_in[q + 5];
            p.gx[i]   = (const int*)d_in[q + 6];
            p.tc[i]   = (const int*)d_in[q + 7];
            p.tbox[i] = (const float*)d_in[q + 8];
            p.anc[i]  = (const float*)d_in[q + 9];
        }
    }

    k_fused<<<GRID_TOT, 256>>>(p, (float*)d_out);
}

// round 6
// speedup vs baseline: 1.2326x; 1.2326x over previous
#include <cuda_runtime.h>
#include <math.h>

// ---------------- constants ----------------
#define NC 80
#define M0 614400
#define M1 153600
#define M2 38400
#define MTOT 806400

#define N0 6000
#define N1 4000
#define N2 2000
#define NT 12000

#define EPSV 1e-7f

// block layout for k1: warp-per-target blocks (8 warps each), then dense float4 blocks
#define T0_BLK 750            // 6000/8
#define T1_BLK 500            // 4000/8
#define T2_BLK 250            // 2000/8
#define T_BLOCKS (T0_BLK+T1_BLK+T2_BLK)      // 1500
#define D0_BLK 600            // 600*256 = 153600 = M0/4
#define D1_BLK 150            // 150*256 =  38400 = M1/4
#define D2_BLK 38             //  38*256 =   9728 >= 9600 = M2/4
#define D_BLOCKS (D0_BLK+D1_BLK+D2_BLK)      // 788
#define GRID_TOT (T_BLOCKS + D_BLOCKS)       // 2288

// ---------------- scratch (no allocations allowed) ----------------
__device__ float g_tobj[MTOT];   // zero at load; k2 restores touched cells to zero
__device__ int   g_cells[NT];
__device__ float g_pTb[T_BLOCKS];
__device__ float g_pTc[T_BLOCKS];
__device__ float g_pTo[T_BLOCKS];
__device__ float g_pD[D_BLOCKS];

// ---------------- params ----------------
struct P {
    const float* box[3]; const float* cnf[3]; const float* cls[3];
    const float* tbox[3]; const float* anc[3];
    const int* b[3]; const int* a[3]; const int* gy[3]; const int* gx[3]; const int* tc[3];
};

// ---------------- helpers ----------------
__device__ __forceinline__ float sp(float x) {   // softplus = bce(x,0), fast
    return fmaxf(x, 0.f) + __logf(1.f + __expf(-fabsf(x)));
}
__device__ __forceinline__ float sigf(float x) {
    return __fdividef(1.f, 1.f + __expf(-x));
}

__device__ __forceinline__ float ciou(float cx1, float cy1, float w1, float h1,
                                      float cx2, float cy2, float w2, float h2) {
    float x1a = cx1 - w1 * 0.5f, y1a = cy1 - h1 * 0.5f;
    float x2a = cx1 + w1 * 0.5f, y2a = cy1 + h1 * 0.5f;
    float x1b = cx2 - w2 * 0.5f, y1b = cy2 - h2 * 0.5f;
    float x2b = cx2 + w2 * 0.5f, y2b = cy2 + h2 * 0.5f;

    float iw = fmaxf(fminf(x2a, x2b) - fmaxf(x1a, x1b), 0.f);
    float ih = fmaxf(fminf(y2a, y2b) - fmaxf(y1a, y1b), 0.f);
    float inter = iw * ih;
    float uni = (x2a - x1a) * (y2a - y1a) + (x2b - x1b) * (y2b - y1b) - inter;
    float iou = __fdividef(inter, uni + EPSV);

    float cw = fmaxf(x2a, x2b) - fminf(x1a, x1b);
    float ch = fmaxf(y2a, y2b) - fminf(y1a, y1b);
    float diag = cw * cw + ch * ch + EPSV;
    float dx = (x1a + x2a) * 0.5f - (x1b + x2b) * 0.5f;
    float dy = (y1a + y2a) * 0.5f - (y1b + y2b) * 0.5f;
    float cent = dx * dx + dy * dy;

    float at = atanf(__fdividef(x2a - x1a, y2a - y1a + EPSV))
             - atanf(__fdividef(x2b - x1b, y2b - y1b + EPSV));
    const float C4PI2 = 4.0f / (float)(M_PI * M_PI);
    float v = C4PI2 * at * at;
    float alpha = __fdividef(v, v - iou + 1.f + EPSV);
    return iou - (__fdividef(cent, diag) + v * alpha);
}

// ---------------- per-scale compile-time constants ----------------
template<int SI> struct SC;
template<> struct SC<0> { static constexpr int DIM=80, OFF=0,     NSC=N0, G0=0;     static constexpr float W=4.0f/(float)M0; };
template<> struct SC<1> { static constexpr int DIM=40, OFF=M0,    NSC=N1, G0=N0;    static constexpr float W=1.0f/(float)M1; };
template<> struct SC<2> { static constexpr int DIM=20, OFF=M0+M1, NSC=N2, G0=N0+N1; static constexpr float W=0.4f/(float)M2; };

// ---------------- target block (warp per target), compile-time SI ----------
template<int SI>
__device__ __forceinline__ void target_block(const P& __restrict__ p, int bid0, unsigned bx) {
    __shared__ float sh[24];
    const int tid  = threadIdx.x;
    const int lane = tid & 31;
    const int wid  = tid >> 5;

    const int t = ((int)bx - bid0) * 8 + wid;            // scale-local target
    constexpr int DIM = SC<SI>::DIM;
    constexpr float INV_N  = 1.f / (float)SC<SI>::NSC;
    constexpr float INV_NC = 1.f / ((float)SC<SI>::NSC * (float)NC);

    int bb = p.b[SI][t], aa = p.a[SI][t];
    int yy = p.gy[SI][t], xx = p.gx[SI][t];
    int tc = p.tc[SI][t];
    int base = ((bb * 3 + aa) * DIM + yy) * DIM + xx;

    // class-row softplus sum across lanes 0..19 (float4 each)
    const float4* crow = (const float4*)(p.cls[SI] + (size_t)base * NC);
    float4 x = make_float4(0.f, 0.f, 0.f, 0.f);
    float s = 0.f;
    if (lane < 20) {
        x = crow[lane];
        s = sp(x.x) + sp(x.y) + sp(x.z) + sp(x.w);
    }
    // extract x_tc from the already-loaded row
    float comp = (tc & 2) ? ((tc & 1) ? x.w : x.z) : ((tc & 1) ? x.y : x.x);
    float xtc  = __shfl_sync(0xffffffffu, comp, tc >> 2);

    #pragma unroll
    for (int o = 16; o; o >>= 1)
        s += __shfl_down_sync(0xffffffffu, s, o);

    if (lane == 0) {
        float4 br = ((const float4*)p.box[SI])[base];
        float2 an = ((const float2*)p.anc[SI])[t];
        float4 tb = ((const float4*)p.tbox[SI])[t];

        float px  = sigf(br.x) * 2.f - 0.5f;
        float py  = sigf(br.y) * 2.f - 0.5f;
        float sw  = sigf(br.z) * 2.f;
        float shh = sigf(br.w) * 2.f;
        float pw  = sw * sw * an.x;
        float ph  = shh * shh * an.y;

        float ci = ciou(px, py, pw, ph, tb.x, tb.y, tb.z, tb.w);
        float v  = fmaxf(ci, 0.f);

        int cell = SC<SI>::OFF + base;
        float old = atomicExch(&g_tobj[cell], v);   // telescoping winner semantics (exact)
        g_cells[SC<SI>::G0 + t] = cell;

        sh[wid]      = (1.f - ci) * INV_N;                      // lbox
        sh[8 + wid]  = (s - xtc) * INV_NC;                      // lcls
        sh[16 + wid] = p.cnf[SI][base] * (v - old) * SC<SI>::W; // lobj correction (subtract)
    }
    __syncthreads();
    if (tid == 0) {
        float a = 0.f, b = 0.f, c = 0.f;
        #pragma unroll
        for (int i = 0; i < 8; i++) { a += sh[i]; b += sh[8 + i]; c += sh[16 + i]; }
        g_pTb[bx] = a; g_pTc[bx] = b; g_pTo[bx] = c;
    }
}

// ---------------- dense block (float4 softplus), compile-time SI -----------
template<int SI>
__device__ __forceinline__ void dense_block(const P& __restrict__ p, int db_local, unsigned bx) {
    __shared__ float sh[8];
    const int tid  = threadIdx.x;
    const int lane = tid & 31;
    const int wid  = tid >> 5;

    constexpr int Q = (SI == 0 ? M0 : (SI == 1 ? M1 : M2)) / 4;
    int i4 = db_local * 256 + tid;
    float acc = 0.f;
    if (SI != 2 || i4 < Q) {
        float4 x = ((const float4*)p.cnf[SI])[i4];
        acc = sp(x.x) + sp(x.y) + sp(x.z) + sp(x.w);
    }
    #pragma unroll
    for (int o = 16; o; o >>= 1)
        acc += __shfl_down_sync(0xffffffffu, acc, o);
    if (lane == 0) sh[wid] = acc;
    __syncthreads();
    if (tid == 0) {
        float a = 0.f;
        #pragma unroll
        for (int i = 0; i < 8; i++) a += sh[i];
        g_pD[bx - T_BLOCKS] = a * SC<SI>::W;
    }
}

// ---------------- kernel 1: all parallel work ----------------
__global__ void __launch_bounds__(256) k_main(P p) {
    const unsigned bx = blockIdx.x;
    if (bx < T_BLOCKS) {
        if (bx < T0_BLK)               target_block<0>(p, 0, bx);
        else if (bx < T0_BLK + T1_BLK) target_block<1>(p, T0_BLK, bx);
        else                           target_block<2>(p, T0_BLK + T1_BLK, bx);
    } else {
        int db = (int)bx - T_BLOCKS;
        if (db < D0_BLK)               dense_block<0>(p, db, bx);
        else if (db < D0_BLK + D1_BLK) dense_block<1>(p, db - D0_BLK, bx);
        else                           dense_block<2>(p, db - D0_BLK - D1_BLK, bx);
    }
}

// ---------------- kernel 2: cleanup + final reduce (1 block) ----------------
__global__ void __launch_bounds__(1024) k_final(float* __restrict__ out) {
    const int tid  = threadIdx.x;
    const int lane = tid & 31;
    const int wid  = tid >> 5;

    // restore g_tobj to zero for the next graph replay (plain stores; dups benign)
    #pragma unroll
    for (int i = tid; i < NT; i += 1024) g_tobj[g_cells[i]] = 0.f;

    double lb = 0.0, lc = 0.0, lo = 0.0;
    for (int i = tid; i < T_BLOCKS; i += 1024) {
        lb += (double)g_pTb[i];
        lc += (double)g_pTc[i];
        lo -= (double)g_pTo[i];
    }
    for (int i = tid; i < D_BLOCKS; i += 1024) lo += (double)g_pD[i];

    #pragma unroll
    for (int o = 16; o; o >>= 1) {
        lb += __shfl_down_sync(0xffffffffu, lb, o);
        lc += __shfl_down_sync(0xffffffffu, lc, o);
        lo += __shfl_down_sync(0xffffffffu, lo, o);
    }
    __shared__ double shd[96];
    if (lane == 0) { shd[wid] = lb; shd[32 + wid] = lc; shd[64 + wid] = lo; }
    __syncthreads();
    if (wid == 0) {
        double b = shd[lane], c = shd[32 + lane], o = shd[64 + lane];
        #pragma unroll
        for (int of = 16; of; of >>= 1) {
            b += __shfl_down_sync(0xffffffffu, b, of);
            c += __shfl_down_sync(0xffffffffu, c, of);
            o += __shfl_down_sync(0xffffffffu, o, of);
        }
        if (lane == 0) {
            out[0] = (float)(b * 1.6);    // 0.05 * 32
            out[1] = (float)(o * 22.4);   // 0.70 * 32
            out[2] = (float)(c * 9.6);    // 0.30 * 32
        }
    }
}

// ---------------- launch ----------------
extern "C" void kernel_launch(void* const* d_in, const int* in_sizes, int n_in,
                              void* d_out, int out_size) {
    // Disambiguate metadata ordering via in_sizes[3]:
    //  (A) reference-arg order -> in_sizes[3] == 24000 (tbox0)
    //  (B) setup_inputs insertion order per scale [box,cnf,cls,b,a,gy,gx,tcls,tbox,anc] -> 6000 (b0)
    P p;
    bool orderA = (n_in > 3 && in_sizes[3] == 24000);
    if (orderA) {
        for (int i = 0; i < 3; i++) {
            int f = 5 * i, g = 15 + 5 * i;
            p.box[i]  = (const float*)d_in[f + 0];
            p.cnf[i]  = (const float*)d_in[f + 1];
            p.cls[i]  = (const float*)d_in[f + 2];
            p.tbox[i] = (const float*)d_in[f + 3];
            p.anc[i]  = (const float*)d_in[f + 4];
            p.b[i]    = (const int*)d_in[g + 0];
            p.a[i]    = (const int*)d_in[g + 1];
            p.gy[i]   = (const int*)d_in[g + 2];
            p.gx[i]   = (const int*)d_in[g + 3];
            p.tc[i]   = (const int*)d_in[g + 4];
        }
    } else {
        for (int i = 0; i < 3; i++) {
            int q = 10 * i;
            p.box[i]  = (const float*)d_in[q + 0];
            p.cnf[i]  = (const float*)d_in[q + 1];
            p.cls[i]  = (const float*)d_in[q + 2];
            p.b[i]    = (const int*)d_in[q + 3];
            p.a[i]    = (const int*)d_in[q + 4];
            p.gy[i]   = (const int*)d_in[q + 5];
            p.gx[i]   = (const int*)d_in[q + 6];
            p.tc[i]   = (const int*)d_in[q + 7];
            p.tbox[i] = (const float*)d_in[q + 8];
            p.anc[i]  = (const float*)d_in[q + 9];
        }
    }

    k_main<<<GRID_TOT, 256>>>(p);
    k_final<<<1, 1024>>>((float*)d_out);
}

// round 7
// speedup vs baseline: 1.8224x; 1.4785x over previous
#include <cuda_runtime.h>
#include <math.h>

// ---------------- constants ----------------
#define NC 80
#define M0 614400
#define M1 153600
#define M2 38400
#define MTOT 806400

#define N0 6000
#define N1 4000
#define N2 2000
#define NT 12000

#define EPSV 1e-7f

// block layout for k_main: warp-per-target blocks (8 warps each), then dense float4 blocks
#define T0_BLK 750            // 6000/8
#define T1_BLK 500            // 4000/8
#define T2_BLK 250            // 2000/8
#define T_BLOCKS (T0_BLK+T1_BLK+T2_BLK)      // 1500
#define D0_BLK 600            // 600*256 = 153600 = M0/4
#define D1_BLK 150            // 150*256 =  38400 = M1/4
#define D2_BLK 38             //  38*256 =   9728 >= 9600 = M2/4
#define D_BLOCKS (D0_BLK+D1_BLK+D2_BLK)      // 788
#define GRID_TOT (T_BLOCKS + D_BLOCKS)       // 2288

#define F_BLOCKS 48           // k_fin blocks: 48*256 = 12288 >= NT

// ---------------- scratch (no allocations allowed) ----------------
__device__ float    g_tobj[MTOT];   // zero at load; k_fin restores touched cells to zero
__device__ int      g_cells[NT];
__device__ float    g_pTb[T_BLOCKS];
__device__ float    g_pTc[T_BLOCKS];
__device__ float    g_pTo[T_BLOCKS];
__device__ float    g_pD[D_BLOCKS];
__device__ double   g_s2[3 * F_BLOCKS];   // stage-2 partials (fully overwritten each run)
__device__ unsigned g_ticket;             // zero at load; last block resets

// ---------------- params ----------------
struct P {
    const float* box[3]; const float* cnf[3]; const float* cls[3];
    const float* tbox[3]; const float* anc[3];
    const int* b[3]; const int* a[3]; const int* gy[3]; const int* gx[3]; const int* tc[3];
};

// ---------------- helpers ----------------
__device__ __forceinline__ float sp(float x) {   // softplus = bce(x,0), fast
    return fmaxf(x, 0.f) + __logf(1.f + __expf(-fabsf(x)));
}
__device__ __forceinline__ float sigf(float x) {
    return __fdividef(1.f, 1.f + __expf(-x));
}

__device__ __forceinline__ float ciou(float cx1, float cy1, float w1, float h1,
                                      float cx2, float cy2, float w2, float h2) {
    float x1a = cx1 - w1 * 0.5f, y1a = cy1 - h1 * 0.5f;
    float x2a = cx1 + w1 * 0.5f, y2a = cy1 + h1 * 0.5f;
    float x1b = cx2 - w2 * 0.5f, y1b = cy2 - h2 * 0.5f;
    float x2b = cx2 + w2 * 0.5f, y2b = cy2 + h2 * 0.5f;

    float iw = fmaxf(fminf(x2a, x2b) - fmaxf(x1a, x1b), 0.f);
    float ih = fmaxf(fminf(y2a, y2b) - fmaxf(y1a, y1b), 0.f);
    float inter = iw * ih;
    float uni = (x2a - x1a) * (y2a - y1a) + (x2b - x1b) * (y2b - y1b) - inter;
    float iou = __fdividef(inter, uni + EPSV);

    float cw = fmaxf(x2a, x2b) - fminf(x1a, x1b);
    float ch = fmaxf(y2a, y2b) - fminf(y1a, y1b);
    float diag = cw * cw + ch * ch + EPSV;
    float dx = (x1a + x2a) * 0.5f - (x1b + x2b) * 0.5f;
    float dy = (y1a + y2a) * 0.5f - (y1b + y2b) * 0.5f;
    float cent = dx * dx + dy * dy;

    float at = atanf(__fdividef(x2a - x1a, y2a - y1a + EPSV))
             - atanf(__fdividef(x2b - x1b, y2b - y1b + EPSV));
    const float C4PI2 = 4.0f / (float)(M_PI * M_PI);
    float v = C4PI2 * at * at;
    float alpha = __fdividef(v, v - iou + 1.f + EPSV);
    return iou - (__fdividef(cent, diag) + v * alpha);
}

// ---------------- per-scale compile-time constants ----------------
template<int SI> struct SC;
template<> struct SC<0> { static constexpr int DIM=80, OFF=0,     NSC=N0, G0=0;     static constexpr float W=4.0f/(float)M0; };
template<> struct SC<1> { static constexpr int DIM=40, OFF=M0,    NSC=N1, G0=N0;    static constexpr float W=1.0f/(float)M1; };
template<> struct SC<2> { static constexpr int DIM=20, OFF=M0+M1, NSC=N2, G0=N0+N1; static constexpr float W=0.4f/(float)M2; };

// ---------------- target block (warp per target), compile-time SI ----------
template<int SI>
__device__ __forceinline__ void target_block(const P& __restrict__ p, int bid0, unsigned bx) {
    __shared__ float sh[24];
    const int tid  = threadIdx.x;
    const int lane = tid & 31;
    const int wid  = tid >> 5;

    const int t = ((int)bx - bid0) * 8 + wid;            // scale-local target
    constexpr int DIM = SC<SI>::DIM;
    constexpr float INV_N  = 1.f / (float)SC<SI>::NSC;
    constexpr float INV_NC = 1.f / ((float)SC<SI>::NSC * (float)NC);

    int bb = p.b[SI][t], aa = p.a[SI][t];
    int yy = p.gy[SI][t], xx = p.gx[SI][t];
    int tc = p.tc[SI][t];
    int base = ((bb * 3 + aa) * DIM + yy) * DIM + xx;

    // class-row softplus sum across lanes 0..19 (float4 each)
    const float4* crow = (const float4*)(p.cls[SI] + (size_t)base * NC);
    float4 x = make_float4(0.f, 0.f, 0.f, 0.f);
    float s = 0.f;
    if (lane < 20) {
        x = crow[lane];
        s = sp(x.x) + sp(x.y) + sp(x.z) + sp(x.w);
    }
    // extract x_tc from the already-loaded row
    float comp = (tc & 2) ? ((tc & 1) ? x.w : x.z) : ((tc & 1) ? x.y : x.x);
    float xtc  = __shfl_sync(0xffffffffu, comp, tc >> 2);

    #pragma unroll
    for (int o = 16; o; o >>= 1)
        s += __shfl_down_sync(0xffffffffu, s, o);

    if (lane == 0) {
        float4 br = ((const float4*)p.box[SI])[base];
        float2 an = ((const float2*)p.anc[SI])[t];
        float4 tb = ((const float4*)p.tbox[SI])[t];

        float px  = sigf(br.x) * 2.f - 0.5f;
        float py  = sigf(br.y) * 2.f - 0.5f;
        float sw  = sigf(br.z) * 2.f;
        float shh = sigf(br.w) * 2.f;
        float pw  = sw * sw * an.x;
        float ph  = shh * shh * an.y;

        float ci = ciou(px, py, pw, ph, tb.x, tb.y, tb.z, tb.w);
        float v  = fmaxf(ci, 0.f);

        int cell = SC<SI>::OFF + base;
        float old = atomicExch(&g_tobj[cell], v);   // telescoping winner semantics (exact)
        g_cells[SC<SI>::G0 + t] = cell;

        sh[wid]      = (1.f - ci) * INV_N;                      // lbox
        sh[8 + wid]  = (s - xtc) * INV_NC;                      // lcls
        sh[16 + wid] = p.cnf[SI][base] * (v - old) * SC<SI>::W; // lobj correction (subtract)
    }
    __syncthreads();
    if (tid == 0) {
        float a = 0.f, b = 0.f, c = 0.f;
        #pragma unroll
        for (int i = 0; i < 8; i++) { a += sh[i]; b += sh[8 + i]; c += sh[16 + i]; }
        g_pTb[bx] = a; g_pTc[bx] = b; g_pTo[bx] = c;
    }
}

// ---------------- dense block (float4 softplus), compile-time SI -----------
template<int SI>
__device__ __forceinline__ void dense_block(const P& __restrict__ p, int db_local, unsigned bx) {
    __shared__ float sh[8];
    const int tid  = threadIdx.x;
    const int lane = tid & 31;
    const int wid  = tid >> 5;

    constexpr int Q = (SI == 0 ? M0 : (SI == 1 ? M1 : M2)) / 4;
    int i4 = db_local * 256 + tid;
    float acc = 0.f;
    if (SI != 2 || i4 < Q) {
        float4 x = ((const float4*)p.cnf[SI])[i4];
        acc = sp(x.x) + sp(x.y) + sp(x.z) + sp(x.w);
    }
    #pragma unroll
    for (int o = 16; o; o >>= 1)
        acc += __shfl_down_sync(0xffffffffu, acc, o);
    if (lane == 0) sh[wid] = acc;
    __syncthreads();
    if (tid == 0) {
        float a = 0.f;
        #pragma unroll
        for (int i = 0; i < 8; i++) a += sh[i];
        g_pD[bx - T_BLOCKS] = a * SC<SI>::W;
    }
}

// ---------------- kernel 1: all parallel work ----------------
__global__ void __launch_bounds__(256) k_main(P p) {
    const unsigned bx = blockIdx.x;
    if (bx < T_BLOCKS) {
        if (bx < T0_BLK)               target_block<0>(p, 0, bx);
        else if (bx < T0_BLK + T1_BLK) target_block<1>(p, T0_BLK, bx);
        else                           target_block<2>(p, T0_BLK + T1_BLK, bx);
    } else {
        int db = (int)bx - T_BLOCKS;
        if (db < D0_BLK)               dense_block<0>(p, db, bx);
        else if (db < D0_BLK + D1_BLK) dense_block<1>(p, db - D0_BLK, bx);
        else                           dense_block<2>(p, db - D0_BLK - D1_BLK, bx);
    }
}

// ---------------- kernel 2: parallel cleanup + two-stage reduce ------------
__global__ void __launch_bounds__(256) k_fin(float* __restrict__ out) {
    const int tid  = threadIdx.x;
    const int lane = tid & 31;
    const int wid  = tid >> 5;
    const int bx   = blockIdx.x;
    const int gi   = bx * 256 + tid;    // 0 .. 12287

    // parallel cleanup: restore touched g_tobj cells to zero (dups benign)
    if (gi < NT) g_tobj[g_cells[gi]] = 0.f;

    // stage-1 reduce: each global thread covers at most one element per array
    double lb = 0.0, lc = 0.0, lo = 0.0;
    if (gi < T_BLOCKS) {
        lb =  (double)g_pTb[gi];
        lc =  (double)g_pTc[gi];
        lo = -(double)g_pTo[gi];
    }
    if (gi < D_BLOCKS) lo += (double)g_pD[gi];

    #pragma unroll
    for (int o = 16; o; o >>= 1) {
        lb += __shfl_down_sync(0xffffffffu, lb, o);
        lc += __shfl_down_sync(0xffffffffu, lc, o);
        lo += __shfl_down_sync(0xffffffffu, lo, o);
    }
    __shared__ double shd[24];
    if (lane == 0) { shd[wid] = lb; shd[8 + wid] = lc; shd[16 + wid] = lo; }
    __syncthreads();
    if (tid == 0) {
        double b = 0.0, c = 0.0, o = 0.0;
        #pragma unroll
        for (int i = 0; i < 8; i++) { b += shd[i]; c += shd[8 + i]; o += shd[16 + i]; }
        g_s2[bx]                 = b;
        g_s2[F_BLOCKS + bx]      = c;
        g_s2[2 * F_BLOCKS + bx]  = o;
    }

    // ticket: last of 48 blocks does the tiny stage-2 sum (cheap at this scale)
    __shared__ unsigned s_rank;
    __threadfence();
    if (tid == 0) s_rank = atomicAdd(&g_ticket, 1u);
    __syncthreads();
    if (s_rank == F_BLOCKS - 1) {
        __threadfence();
        if (wid == 0) {
            double b = 0.0, c = 0.0, o = 0.0;
            if (lane < F_BLOCKS) {   // F_BLOCKS > 32: two strides of 32 via loop
                // lane covers lane and lane+32 (if valid)
                b = g_s2[lane];
                c = g_s2[F_BLOCKS + lane];
                o = g_s2[2 * F_BLOCKS + lane];
            }
            int l2 = lane + 32;
            if (l2 < F_BLOCKS) {
                b += g_s2[l2];
                c += g_s2[F_BLOCKS + l2];
                o += g_s2[2 * F_BLOCKS + l2];
            }
            #pragma unroll
            for (int of = 16; of; of >>= 1) {
                b += __shfl_down_sync(0xffffffffu, b, of);
                c += __shfl_down_sync(0xffffffffu, c, of);
                o += __shfl_down_sync(0xffffffffu, o, of);
            }
            if (lane == 0) {
                out[0] = (float)(b * 1.6);    // 0.05 * 32
                out[1] = (float)(o * 22.4);   // 0.70 * 32
                out[2] = (float)(c * 9.6);    // 0.30 * 32
                g_ticket = 0;                 // reset for next replay
            }
        }
    }
}

// ---------------- launch ----------------
extern "C" void kernel_launch(void* const* d_in, const int* in_sizes, int n_in,
                              void* d_out, int out_size) {
    // Disambiguate metadata ordering via in_sizes[3]:
    //  (A) reference-arg order -> in_sizes[3] == 24000 (tbox0)
    //  (B) setup_inputs insertion order per scale [box,cnf,cls,b,a,gy,gx,tcls,tbox,anc] -> 6000 (b0)
    P p;
    bool orderA = (n_in > 3 && in_sizes[3] == 24000);
    if (orderA) {
        for (int i = 0; i < 3; i++) {
            int f = 5 * i, g = 15 + 5 * i;
            p.box[i]  = (const float*)d_in[f + 0];
            p.cnf[i]  = (const float*)d_in[f + 1];
            p.cls[i]  = (const float*)d_in[f + 2];
            p.tbox[i] = (const float*)d_in[f + 3];
            p.anc[i]  = (const float*)d_in[f + 4];
            p.b[i]    = (const int*)d_in[g + 0];
            p.a[i]    = (const int*)d_in[g + 1];
            p.gy[i]   = (const int*)d_in[g + 2];
            p.gx[i]   = (const int*)d_in[g + 3];
            p.tc[i]   = (const int*)d_in[g + 4];
        }
    } else {
        for (int i = 0; i < 3; i++) {
            int q = 10 * i;
            p.box[i]  = (const float*)d_in[q + 0];
            p.cnf[i]  = (const float*)d_in[q + 1];
            p.cls[i]  = (const float*)d_in[q + 2];
            p.b[i]    = (const int*)d_in[q + 3];
            p.a[i]    = (const int*)d_in[q + 4];
            p.gy[i]   = (const int*)d_in[q + 5];
            p.gx[i]   = (const int*)d_in[q + 6];
            p.tc[i]   = (const int*)d_in[q + 7];
            p.tbox[i] = (const float*)d_in[q + 8];
            p.anc[i]  = (const float*)d_in[q + 9];
        }
    }

    k_main<<<GRID_TOT, 256>>>(p);
    k_fin<<<F_BLOCKS, 256>>>((float*)d_out);
}